// round 13
// baseline (speedup 1.0000x reference)
#include <cuda_runtime.h>
#include <math.h>
#include <float.h>
#include <stdint.h>

#define N_SAMPLES 8192
#define DIM 128
#define NCLUST 64
#define TILE_I 128
#define TILE_J 64
#define NTJ (N_SAMPLES / TILE_J)    // 128
#define NPAIRS 4160
#define KS 16
#define NSLAB (DIM / KS)            // 8

// smem (floats): A-dup slabs 16k x 128row x 2 = 4096 floats (16KB) each,
// B slabs 16x64 = 1024 floats (4KB) each
#define AD0 0
#define AD1 4096
#define BS0 8192
#define BS1 9216
#define SMEM_FLOATS 10240           // 40KB -> 3 CTAs/SM

typedef unsigned long long ull;
__device__ int   g_lab[N_SAMPLES];
__device__ int   g_labS[N_SAMPLES];
__device__ int   g_perm[N_SAMPLES];
__device__ float g_sqS[N_SAMPLES];
__device__ float g_FpT[DIM * N_SAMPLES];    // sorted, k-major (B loads)
__device__ ull   g_FpTd[DIM * N_SAMPLES];   // sorted, k-major, dup pairs (A loads)
__device__ int   g_counts[NCLUST];
__device__ float g_S[NCLUST * N_SAMPLES];
__device__ float g_partial[32];

__device__ __forceinline__ void fma2(ull& acc, ull a, ull b) {
    asm("fma.rn.f32x2 %0, %1, %2, %0;" : "+l"(acc) : "l"(a), "l"(b));
}
__device__ __forceinline__ ull dup2(float a) {
    ull r;
    asm("mov.b64 %0, {%1, %1};" : "=l"(r) : "f"(a));
    return r;
}
__device__ __forceinline__ uint32_t smem_u32(const void* p) {
    uint32_t a;
    asm("{ .reg .u64 t; cvta.to.shared.u64 t, %1; cvt.u32.u64 %0, t; }"
        : "=r"(a) : "l"(p));
    return a;
}
__device__ __forceinline__ void cp16(uint32_t dst, const void* src) {
    asm volatile("cp.async.cg.shared.global [%0], [%1], 16;"
                 :: "r"(dst), "l"(src) : "memory");
}
#define CP_COMMIT() asm volatile("cp.async.commit_group;" ::: "memory")
#define CP_WAIT1()  asm volatile("cp.async.wait_group 1;" ::: "memory")
#define CP_WAIT0()  asm volatile("cp.async.wait_group 0;" ::: "memory")

// ---------------------------------------------------------------------------
__global__ void conv_labels_kernel(const int* __restrict__ Lraw) {
    __shared__ int is64;
    if (threadIdx.x == 0) {
        int odd_or = 0, even_bad = 0;
        for (int k = 0; k < 256; k += 2) {
            odd_or   |= Lraw[k + 1];
            even_bad |= ((unsigned)Lraw[k] >= NCLUST);
        }
        is64 = (odd_or == 0 && !even_bad) ? 1 : 0;
    }
    __syncthreads();
    const int w = is64;
    for (int i = threadIdx.x; i < N_SAMPLES; i += blockDim.x) {
        int v = w ? Lraw[2 * i] : Lraw[i];
        g_lab[i] = min(max(v, 0), NCLUST - 1);
    }
}

__global__ void sort_kernel() {
    __shared__ unsigned short T[256][NCLUST];
    __shared__ int colTot[NCLUST];
    __shared__ int cbase[NCLUST];
    const int s = threadIdx.x;
#pragma unroll
    for (int c = 0; c < NCLUST; c++) T[s][c] = 0;
    const int e0 = s * 32;
    for (int e = 0; e < 32; e++) T[s][g_lab[e0 + e]]++;
    __syncthreads();
    if (s < NCLUST) {
        int tot = 0;
        for (int q = 0; q < 256; q++) tot += T[q][s];
        colTot[s] = tot;
        g_counts[s] = tot;
    }
    __syncthreads();
    if (s == 0) {
        int run = 0;
        for (int c = 0; c < NCLUST; c++) { cbase[c] = run; run += colTot[c]; }
    }
    __syncthreads();
    if (s < NCLUST) {
        int run = cbase[s];
        for (int q = 0; q < 256; q++) {
            int w = T[q][s];
            T[q][s] = (unsigned short)run;
            run += w;
        }
    }
    __syncthreads();
    for (int e = 0; e < 32; e++) {
        int idx = e0 + e;
        int c = g_lab[idx];
        int p = T[s][c]++;
        g_perm[p] = idx;
        g_labS[p] = c;
    }
}

__global__ void gatherT_kernel(const float* __restrict__ F) {
    __shared__ float T[32][DIM + 1];
    const int tid = threadIdx.x;
    const int lane = tid & 31, w = tid >> 5;
    const int base = blockIdx.x * 32;
#pragma unroll
    for (int rr = 0; rr < 4; rr++) {
        const int p = base + w * 4 + rr;
        const int src = g_perm[p];
        float4 v = reinterpret_cast<const float4*>(F)[src * 32 + lane];
        T[w * 4 + rr][lane * 4 + 0] = v.x;
        T[w * 4 + rr][lane * 4 + 1] = v.y;
        T[w * 4 + rr][lane * 4 + 2] = v.z;
        T[w * 4 + rr][lane * 4 + 3] = v.w;
        float s = v.x * v.x + v.y * v.y + v.z * v.z + v.w * v.w;
#pragma unroll
        for (int o = 16; o > 0; o >>= 1) s += __shfl_down_sync(0xffffffffu, s, o);
        if (lane == 0) g_sqS[p] = s;
    }
    __syncthreads();
    const int i = tid & 31, ksub = tid >> 5;
#pragma unroll
    for (int step = 0; step < 16; step++) {
        int k = step * 8 + ksub;
        float v = T[i][k];
        g_FpT[(size_t)k * N_SAMPLES + base + i] = v;
        g_FpTd[(size_t)k * N_SAMPLES + base + i] = dup2(v);
    }
}

__global__ void zeroS_kernel() {
    g_S[blockIdx.x * 1024 + threadIdx.x] = 0.f;
}

// ---------------------------------------------------------------------------
// dist: 128x64 half-tile per CTA, jh >= 2*it. 8x4 reg tiles, FFMA2 with
// pre-duplicated A operands from smem (no MOV dup chain), cp.async slabs,
// epilogue: run-length label sums -> global atomics into L2-resident g_S.
__global__ __launch_bounds__(256, 3) void dist_kernel() {
    int it = 0, rem = blockIdx.x, cnt = NTJ;
    while (rem >= cnt) { rem -= cnt; cnt -= 2; it++; }
    const int jh = 2 * it + rem;
    const bool diagLike = (rem < 2);

    extern __shared__ __align__(16) float smem[];
    const uint32_t sb = smem_u32(smem);
    const int tid = threadIdx.x;
    const int tx = tid & 15, ty = tid >> 4;
    const int iBase = it * TILE_I;
    const int jBase = jh * TILE_J;

    // A-dup slab: KS*128 ull = 1024 16B-chunks -> 4/thread.
    // B slab: KS*64 floats = 256 16B-chunks -> 1/thread.
#define ISSUE_SLAB(u)                                                         \
    {                                                                         \
        const int _b = (u) & 1;                                               \
        const ull* srcA = g_FpTd + (size_t)((u) * KS) * N_SAMPLES + iBase;    \
        const float* srcB = g_FpT + (size_t)((u) * KS) * N_SAMPLES + jBase;   \
        const uint32_t dA = sb + (_b ? AD1 : AD0) * 4;                        \
        const uint32_t dB = sb + (_b ? BS1 : BS0) * 4;                        \
        _Pragma("unroll")                                                     \
        for (int rr = 0; rr < 4; rr++) {                                      \
            int c = tid + rr * 256;                                           \
            int kk = c >> 6, off = c & 63;                                    \
            cp16(dA + (uint32_t)(kk * TILE_I + off * 2) * 8,                  \
                 srcA + (size_t)kk * N_SAMPLES + off * 2);                    \
        }                                                                     \
        {                                                                     \
            int kk = tid >> 4, off = (tid & 15) * 4;                          \
            cp16(dB + (uint32_t)(kk * TILE_J + off) * 4,                      \
                 srcB + (size_t)kk * N_SAMPLES + off);                        \
        }                                                                     \
        CP_COMMIT();                                                          \
    }

    ull acc[16];
#pragma unroll
    for (int z = 0; z < 16; z++) acc[z] = 0ull;

    ISSUE_SLAB(0);
    ISSUE_SLAB(1);
    CP_WAIT1();
    __syncthreads();

#pragma unroll 1
    for (int u = 0; u < NSLAB; u++) {
        const int p = u & 1;
        const ull* Ad = reinterpret_cast<const ull*>(smem + (p ? AD1 : AD0)) + ty * 8;
        const float* bp = smem + (p ? BS1 : BS0) + tx * 4;

#pragma unroll
        for (int k = 0; k < KS; k++) {
            const ull* ak = Ad + k * TILE_I;
            ull a0, a1, a2, a3, a4, a5, a6, a7;
            asm("ld.shared.v2.u64 {%0, %1}, [%2];" : "=l"(a0), "=l"(a1) : "l"(ak));
            asm("ld.shared.v2.u64 {%0, %1}, [%2];" : "=l"(a2), "=l"(a3) : "l"(ak + 2));
            ull b0, b1;
            asm("ld.shared.v2.u64 {%0, %1}, [%2];"
                : "=l"(b0), "=l"(b1) : "l"(bp + k * TILE_J));
            asm("ld.shared.v2.u64 {%0, %1}, [%2];" : "=l"(a4), "=l"(a5) : "l"(ak + 4));
            asm("ld.shared.v2.u64 {%0, %1}, [%2];" : "=l"(a6), "=l"(a7) : "l"(ak + 6));
            fma2(acc[0],  a0, b0); fma2(acc[1],  a0, b1);
            fma2(acc[2],  a1, b0); fma2(acc[3],  a1, b1);
            fma2(acc[4],  a2, b0); fma2(acc[5],  a2, b1);
            fma2(acc[6],  a3, b0); fma2(acc[7],  a3, b1);
            fma2(acc[8],  a4, b0); fma2(acc[9],  a4, b1);
            fma2(acc[10], a5, b0); fma2(acc[11], a5, b1);
            fma2(acc[12], a6, b0); fma2(acc[13], a6, b1);
            fma2(acc[14], a7, b0); fma2(acc[15], a7, b1);
        }
        __syncthreads();
        if (u + 2 < NSLAB) {
            ISSUE_SLAB(u + 2);
            CP_WAIT1();
        } else {
            CP_WAIT0();
        }
        __syncthreads();
    }
#undef ISSUE_SLAB

    // ---- epilogue ----
    float isq[8];
    int   ilr[8];
#pragma unroll
    for (int ii = 0; ii < 8; ii++) {
        const int gi = iBase + ty * 8 + ii;
        isq[ii] = g_sqS[gi];
        ilr[ii] = g_labS[gi];
    }
    int   jlr[4];
    float jsr[4];
#pragma unroll
    for (int jj = 0; jj < 4; jj++) {
        const int gj = jBase + tx * 4 + jj;
        jlr[jj] = g_labS[gj];
        jsr[jj] = g_sqS[gj];
    }

#pragma unroll
    for (int q = 0; q < 16; q++) {
        const int ii = q >> 1, jp = q & 1;
        ull a2 = acc[q];
        float lo = __uint_as_float((unsigned)(a2 & 0xffffffffull));
        float hi = __uint_as_float((unsigned)(a2 >> 32));
        const int gi = iBase + ty * 8 + ii;
        const int gj = jBase + tx * 4 + jp * 2;
        float d2lo = isq[ii] + jsr[jp * 2]     - 2.f * lo;
        float d2hi = isq[ii] + jsr[jp * 2 + 1] - 2.f * hi;
        float dlo = 0.f, dhi = 0.f;
        if (d2lo > 0.f && gi != gj)
            asm("sqrt.approx.f32 %0, %1;" : "=f"(dlo) : "f"(d2lo));
        if (d2hi > 0.f && gi != gj + 1)
            asm("sqrt.approx.f32 %0, %1;" : "=f"(dhi) : "f"(d2hi));
        asm("mov.b64 %0, {%1, %2};" : "=l"(acc[q]) : "f"(dlo), "f"(dhi));
    }

    // i-side: rows gi accumulate over j grouped by sorted j-label
    {
        float run[8];
#pragma unroll
        for (int ii = 0; ii < 8; ii++) run[ii] = 0.f;
        int cur = jlr[0];
#pragma unroll
        for (int jj = 0; jj < 4; jj++) {
            const int c = jlr[jj];
            if (c != cur) {
#pragma unroll
                for (int ii = 0; ii < 8; ii++) {
                    atomicAdd(&g_S[(size_t)cur * N_SAMPLES + iBase + ty * 8 + ii],
                              run[ii]);
                    run[ii] = 0.f;
                }
                cur = c;
            }
            const int jp = jj >> 1;
#pragma unroll
            for (int ii = 0; ii < 8; ii++) {
                ull a2 = acc[ii * 2 + jp];
                float d = (jj & 1) ? __uint_as_float((unsigned)(a2 >> 32))
                                   : __uint_as_float((unsigned)(a2 & 0xffffffffull));
                run[ii] += d;
            }
        }
#pragma unroll
        for (int ii = 0; ii < 8; ii++)
            atomicAdd(&g_S[(size_t)cur * N_SAMPLES + iBase + ty * 8 + ii],
                      run[ii]);
    }

    // j-side (off-diag only): cols gj accumulate over i grouped by i-label
    if (!diagLike) {
        float run[4];
#pragma unroll
        for (int jj = 0; jj < 4; jj++) run[jj] = 0.f;
        int cur = ilr[0];
#pragma unroll
        for (int ii = 0; ii < 8; ii++) {
            const int c = ilr[ii];
            if (c != cur) {
#pragma unroll
                for (int jj = 0; jj < 4; jj++) {
                    atomicAdd(&g_S[(size_t)cur * N_SAMPLES + jBase + tx * 4 + jj],
                              run[jj]);
                    run[jj] = 0.f;
                }
                cur = c;
            }
#pragma unroll
            for (int jj = 0; jj < 4; jj++) {
                ull a2 = acc[ii * 2 + (jj >> 1)];
                float d = (jj & 1) ? __uint_as_float((unsigned)(a2 >> 32))
                                   : __uint_as_float((unsigned)(a2 & 0xffffffffull));
                run[jj] += d;
            }
        }
#pragma unroll
        for (int jj = 0; jj < 4; jj++)
            atomicAdd(&g_S[(size_t)cur * N_SAMPLES + jBase + tx * 4 + jj],
                      run[jj]);
    }
}

// ---------------------------------------------------------------------------
__global__ void score_kernel() {
    const int i = blockIdx.x * 256 + threadIdx.x;
    __shared__ int scounts[NCLUST];
    if (threadIdx.x < NCLUST) scounts[threadIdx.x] = g_counts[threadIdx.x];
    __syncthreads();

    const int own = g_labS[i];
    float Sown = 0.f, b = FLT_MAX;
#pragma unroll
    for (int c = 0; c < NCLUST; c++) {
        float s = g_S[(size_t)c * N_SAMPLES + i];
        int cnt = scounts[c];
        if (c == own) Sown = s;
        else if (cnt > 0) b = fminf(b, s / (float)cnt);
    }
    const int ocnt = scounts[own];
    const float a = Sown / fmaxf((float)ocnt - 1.f, 1.f);
    float score = 0.f;
    if (ocnt > 1) score = (b - a) / fmaxf(b, a);

    __shared__ float red[256];
    red[threadIdx.x] = score;
    __syncthreads();
    for (int s = 128; s > 0; s >>= 1) {
        if (threadIdx.x < s) red[threadIdx.x] += red[threadIdx.x + s];
        __syncthreads();
    }
    if (threadIdx.x == 0) g_partial[blockIdx.x] = red[0];
}

__global__ void final_kernel(float* out) {
    if (threadIdx.x == 0) {
        float s = 0.f;
#pragma unroll
        for (int b = 0; b < 32; b++) s += g_partial[b];
        out[0] = s / (float)N_SAMPLES;
    }
}

// ---------------------------------------------------------------------------
extern "C" void kernel_launch(void* const* d_in, const int* in_sizes, int n_in,
                              void* d_out, int out_size) {
    const float* F = (const float*)d_in[0];
    const int* Lraw = (const int*)d_in[1];
    float* out = (float*)d_out;

    const int smem_bytes = SMEM_FLOATS * 4;   // 40KB -> 3 CTAs/SM
    cudaFuncSetAttribute(dist_kernel,
                         cudaFuncAttributeMaxDynamicSharedMemorySize, smem_bytes);

    conv_labels_kernel<<<1, 256>>>(Lraw);
    sort_kernel<<<1, 256>>>();
    gatherT_kernel<<<N_SAMPLES / 32, 256>>>(F);
    zeroS_kernel<<<NCLUST * N_SAMPLES / 1024, 1024>>>();
    dist_kernel<<<NPAIRS, 256, smem_bytes>>>();
    score_kernel<<<N_SAMPLES / 256, 256>>>();
    final_kernel<<<1, 32>>>(out);
}

// round 14
// speedup vs baseline: 1.2074x; 1.2074x over previous
#include <cuda_runtime.h>
#include <math.h>
#include <float.h>
#include <stdint.h>

#define N_SAMPLES 8192
#define DIM 128
#define NCLUST 64
#define TILE_I 128
#define TILE_J 64
#define NTJ (N_SAMPLES / TILE_J)    // 128
#define NPAIRS 4160
#define KS 16
#define NSLAB (DIM / KS)            // 8

// smem (floats): A slabs 16x128=2048 each, B slabs 16x64=1024 each
#define AS0 0
#define AS1 2048
#define BS0 4096
#define BS1 5120
#define SMEM_FLOATS 6144            // 24KB -> 4 CTAs/SM

typedef unsigned long long ull;
__device__ int   g_lab[N_SAMPLES];
__device__ int   g_labS[N_SAMPLES];
__device__ int   g_perm[N_SAMPLES];
__device__ float g_sqS[N_SAMPLES];
__device__ float g_FpT[DIM * N_SAMPLES];    // sorted, k-major
__device__ int   g_counts[NCLUST];
__device__ float g_S[NCLUST * N_SAMPLES];
__device__ float g_partial[32];

__device__ __forceinline__ void fma2(ull& acc, ull a, ull b) {
    asm("fma.rn.f32x2 %0, %1, %2, %0;" : "+l"(acc) : "l"(a), "l"(b));
}
__device__ __forceinline__ ull dup2(float a) {
    ull r;
    asm("mov.b64 %0, {%1, %1};" : "=l"(r) : "f"(a));
    return r;
}
__device__ __forceinline__ uint32_t smem_u32(const void* p) {
    uint32_t a;
    asm("{ .reg .u64 t; cvta.to.shared.u64 t, %1; cvt.u32.u64 %0, t; }"
        : "=r"(a) : "l"(p));
    return a;
}
__device__ __forceinline__ void cp16(uint32_t dst, const void* src) {
    asm volatile("cp.async.cg.shared.global [%0], [%1], 16;"
                 :: "r"(dst), "l"(src) : "memory");
}
#define CP_COMMIT() asm volatile("cp.async.commit_group;" ::: "memory")
#define CP_WAIT1()  asm volatile("cp.async.wait_group 1;" ::: "memory")
#define CP_WAIT0()  asm volatile("cp.async.wait_group 0;" ::: "memory")

// ---------------------------------------------------------------------------
__global__ void conv_labels_kernel(const int* __restrict__ Lraw) {
    __shared__ int is64;
    if (threadIdx.x == 0) {
        int odd_or = 0, even_bad = 0;
        for (int k = 0; k < 256; k += 2) {
            odd_or   |= Lraw[k + 1];
            even_bad |= ((unsigned)Lraw[k] >= NCLUST);
        }
        is64 = (odd_or == 0 && !even_bad) ? 1 : 0;
    }
    __syncthreads();
    const int w = is64;
    for (int i = threadIdx.x; i < N_SAMPLES; i += blockDim.x) {
        int v = w ? Lraw[2 * i] : Lraw[i];
        g_lab[i] = min(max(v, 0), NCLUST - 1);
    }
}

__global__ void sort_kernel() {
    __shared__ unsigned short T[256][NCLUST];
    __shared__ int colTot[NCLUST];
    __shared__ int cbase[NCLUST];
    const int s = threadIdx.x;
#pragma unroll
    for (int c = 0; c < NCLUST; c++) T[s][c] = 0;
    const int e0 = s * 32;
    for (int e = 0; e < 32; e++) T[s][g_lab[e0 + e]]++;
    __syncthreads();
    if (s < NCLUST) {
        int tot = 0;
        for (int q = 0; q < 256; q++) tot += T[q][s];
        colTot[s] = tot;
        g_counts[s] = tot;
    }
    __syncthreads();
    if (s == 0) {
        int run = 0;
        for (int c = 0; c < NCLUST; c++) { cbase[c] = run; run += colTot[c]; }
    }
    __syncthreads();
    if (s < NCLUST) {
        int run = cbase[s];
        for (int q = 0; q < 256; q++) {
            int w = T[q][s];
            T[q][s] = (unsigned short)run;
            run += w;
        }
    }
    __syncthreads();
    for (int e = 0; e < 32; e++) {
        int idx = e0 + e;
        int c = g_lab[idx];
        int p = T[s][c]++;
        g_perm[p] = idx;
        g_labS[p] = c;
    }
}

__global__ void gatherT_kernel(const float* __restrict__ F) {
    __shared__ float T[32][DIM + 1];
    const int tid = threadIdx.x;
    const int lane = tid & 31, w = tid >> 5;
    const int base = blockIdx.x * 32;
#pragma unroll
    for (int rr = 0; rr < 4; rr++) {
        const int p = base + w * 4 + rr;
        const int src = g_perm[p];
        float4 v = reinterpret_cast<const float4*>(F)[src * 32 + lane];
        T[w * 4 + rr][lane * 4 + 0] = v.x;
        T[w * 4 + rr][lane * 4 + 1] = v.y;
        T[w * 4 + rr][lane * 4 + 2] = v.z;
        T[w * 4 + rr][lane * 4 + 3] = v.w;
        float s = v.x * v.x + v.y * v.y + v.z * v.z + v.w * v.w;
#pragma unroll
        for (int o = 16; o > 0; o >>= 1) s += __shfl_down_sync(0xffffffffu, s, o);
        if (lane == 0) g_sqS[p] = s;
    }
    __syncthreads();
    const int i = tid & 31, ksub = tid >> 5;
#pragma unroll
    for (int step = 0; step < 16; step++) {
        int k = step * 8 + ksub;
        g_FpT[(size_t)k * N_SAMPLES + base + i] = T[i][k];
    }
}

__global__ void zeroS_kernel() {
    g_S[blockIdx.x * 1024 + threadIdx.x] = 0.f;
}

// ---------------------------------------------------------------------------
// dist: 128x64 half-tile per CTA, jh >= 2*it. 8x4 reg tiles, FFMA2 (dup2
// registers), cp.async double-buffered slabs, NO manual prefetch chain --
// latency hidden by 32 warps/SM (__launch_bounds__(256,4)).
__global__ __launch_bounds__(256, 4) void dist_kernel() {
    int it = 0, rem = blockIdx.x, cnt = NTJ;
    while (rem >= cnt) { rem -= cnt; cnt -= 2; it++; }
    const int jh = 2 * it + rem;
    const bool diagLike = (rem < 2);

    extern __shared__ __align__(16) float smem[];
    const uint32_t sb = smem_u32(smem);
    const int tid = threadIdx.x;
    const int tx = tid & 15, ty = tid >> 4;
    const int iBase = it * TILE_I;
    const int jBase = jh * TILE_J;

#define ISSUE_SLAB(u)                                                         \
    {                                                                         \
        const int _b = (u) & 1;                                               \
        const float* srcA = g_FpT + (size_t)((u) * KS) * N_SAMPLES + iBase;   \
        const float* srcB = g_FpT + (size_t)((u) * KS) * N_SAMPLES + jBase;   \
        const uint32_t dA = sb + (_b ? AS1 : AS0) * 4;                        \
        const uint32_t dB = sb + (_b ? BS1 : BS0) * 4;                        \
        _Pragma("unroll")                                                     \
        for (int rr = 0; rr < 2; rr++) {                                      \
            int c = tid + rr * 256;                                           \
            int kk = c >> 5, off = (c & 31) * 4;                              \
            cp16(dA + (uint32_t)(kk * TILE_I + off) * 4,                      \
                 srcA + (size_t)kk * N_SAMPLES + off);                        \
        }                                                                     \
        {                                                                     \
            int kk = tid >> 4, off = (tid & 15) * 4;                          \
            cp16(dB + (uint32_t)(kk * TILE_J + off) * 4,                      \
                 srcB + (size_t)kk * N_SAMPLES + off);                        \
        }                                                                     \
        CP_COMMIT();                                                          \
    }

    ull acc[16];
#pragma unroll
    for (int z = 0; z < 16; z++) acc[z] = 0ull;

    ISSUE_SLAB(0);
    ISSUE_SLAB(1);
    CP_WAIT1();
    __syncthreads();

#pragma unroll 1
    for (int u = 0; u < NSLAB; u++) {
        const int p = u & 1;
        const float* Ab = smem + (p ? AS1 : AS0) + ty * 8;
        const float* bp = smem + (p ? BS1 : BS0) + tx * 4;

#pragma unroll
        for (int k = 0; k < KS; k++) {
            float4 aLo = *reinterpret_cast<const float4*>(Ab + k * TILE_I);
            float4 aHi = *reinterpret_cast<const float4*>(Ab + k * TILE_I + 4);
            ull b0, b1;
            asm("ld.shared.v2.u64 {%0, %1}, [%2];"
                : "=l"(b0), "=l"(b1) : "l"(bp + k * TILE_J));
            ull a;
            a = dup2(aLo.x); fma2(acc[0],  a, b0); fma2(acc[1],  a, b1);
            a = dup2(aLo.y); fma2(acc[2],  a, b0); fma2(acc[3],  a, b1);
            a = dup2(aLo.z); fma2(acc[4],  a, b0); fma2(acc[5],  a, b1);
            a = dup2(aLo.w); fma2(acc[6],  a, b0); fma2(acc[7],  a, b1);
            a = dup2(aHi.x); fma2(acc[8],  a, b0); fma2(acc[9],  a, b1);
            a = dup2(aHi.y); fma2(acc[10], a, b0); fma2(acc[11], a, b1);
            a = dup2(aHi.z); fma2(acc[12], a, b0); fma2(acc[13], a, b1);
            a = dup2(aHi.w); fma2(acc[14], a, b0); fma2(acc[15], a, b1);
        }
        __syncthreads();
        if (u + 2 < NSLAB) {
            ISSUE_SLAB(u + 2);
            CP_WAIT1();
        } else {
            CP_WAIT0();
        }
        __syncthreads();
    }
#undef ISSUE_SLAB

    // ---- epilogue: dots -> distances -> run-length atomics into g_S ----
    float isq[8];
    int   ilr[8];
#pragma unroll
    for (int ii = 0; ii < 8; ii++) {
        const int gi = iBase + ty * 8 + ii;
        isq[ii] = g_sqS[gi];
        ilr[ii] = g_labS[gi];
    }
    int   jlr[4];
    float jsr[4];
#pragma unroll
    for (int jj = 0; jj < 4; jj++) {
        const int gj = jBase + tx * 4 + jj;
        jlr[jj] = g_labS[gj];
        jsr[jj] = g_sqS[gj];
    }

#pragma unroll
    for (int q = 0; q < 16; q++) {
        const int ii = q >> 1, jp = q & 1;
        ull a2 = acc[q];
        float lo = __uint_as_float((unsigned)(a2 & 0xffffffffull));
        float hi = __uint_as_float((unsigned)(a2 >> 32));
        const int gi = iBase + ty * 8 + ii;
        const int gj = jBase + tx * 4 + jp * 2;
        float d2lo = isq[ii] + jsr[jp * 2]     - 2.f * lo;
        float d2hi = isq[ii] + jsr[jp * 2 + 1] - 2.f * hi;
        float dlo = 0.f, dhi = 0.f;
        if (d2lo > 0.f && gi != gj)
            asm("sqrt.approx.f32 %0, %1;" : "=f"(dlo) : "f"(d2lo));
        if (d2hi > 0.f && gi != gj + 1)
            asm("sqrt.approx.f32 %0, %1;" : "=f"(dhi) : "f"(d2hi));
        asm("mov.b64 %0, {%1, %2};" : "=l"(acc[q]) : "f"(dlo), "f"(dhi));
    }

    // i-side: rows gi accumulate over j grouped by sorted j-label
    {
        float run[8];
#pragma unroll
        for (int ii = 0; ii < 8; ii++) run[ii] = 0.f;
        int cur = jlr[0];
#pragma unroll
        for (int jj = 0; jj < 4; jj++) {
            const int c = jlr[jj];
            if (c != cur) {
#pragma unroll
                for (int ii = 0; ii < 8; ii++) {
                    atomicAdd(&g_S[(size_t)cur * N_SAMPLES + iBase + ty * 8 + ii],
                              run[ii]);
                    run[ii] = 0.f;
                }
                cur = c;
            }
            const int jp = jj >> 1;
#pragma unroll
            for (int ii = 0; ii < 8; ii++) {
                ull a2 = acc[ii * 2 + jp];
                float d = (jj & 1) ? __uint_as_float((unsigned)(a2 >> 32))
                                   : __uint_as_float((unsigned)(a2 & 0xffffffffull));
                run[ii] += d;
            }
        }
#pragma unroll
        for (int ii = 0; ii < 8; ii++)
            atomicAdd(&g_S[(size_t)cur * N_SAMPLES + iBase + ty * 8 + ii],
                      run[ii]);
    }

    // j-side (off-diag only): cols gj accumulate over i grouped by i-label
    if (!diagLike) {
        float run[4];
#pragma unroll
        for (int jj = 0; jj < 4; jj++) run[jj] = 0.f;
        int cur = ilr[0];
#pragma unroll
        for (int ii = 0; ii < 8; ii++) {
            const int c = ilr[ii];
            if (c != cur) {
#pragma unroll
                for (int jj = 0; jj < 4; jj++) {
                    atomicAdd(&g_S[(size_t)cur * N_SAMPLES + jBase + tx * 4 + jj],
                              run[jj]);
                    run[jj] = 0.f;
                }
                cur = c;
            }
#pragma unroll
            for (int jj = 0; jj < 4; jj++) {
                ull a2 = acc[ii * 2 + (jj >> 1)];
                float d = (jj & 1) ? __uint_as_float((unsigned)(a2 >> 32))
                                   : __uint_as_float((unsigned)(a2 & 0xffffffffull));
                run[jj] += d;
            }
        }
#pragma unroll
        for (int jj = 0; jj < 4; jj++)
            atomicAdd(&g_S[(size_t)cur * N_SAMPLES + jBase + tx * 4 + jj],
                      run[jj]);
    }
}

// ---------------------------------------------------------------------------
__global__ void score_kernel() {
    const int i = blockIdx.x * 256 + threadIdx.x;
    __shared__ int scounts[NCLUST];
    if (threadIdx.x < NCLUST) scounts[threadIdx.x] = g_counts[threadIdx.x];
    __syncthreads();

    const int own = g_labS[i];
    float Sown = 0.f, b = FLT_MAX;
#pragma unroll
    for (int c = 0; c < NCLUST; c++) {
        float s = g_S[(size_t)c * N_SAMPLES + i];
        int cnt = scounts[c];
        if (c == own) Sown = s;
        else if (cnt > 0) b = fminf(b, s / (float)cnt);
    }
    const int ocnt = scounts[own];
    const float a = Sown / fmaxf((float)ocnt - 1.f, 1.f);
    float score = 0.f;
    if (ocnt > 1) score = (b - a) / fmaxf(b, a);

    __shared__ float red[256];
    red[threadIdx.x] = score;
    __syncthreads();
    for (int s = 128; s > 0; s >>= 1) {
        if (threadIdx.x < s) red[threadIdx.x] += red[threadIdx.x + s];
        __syncthreads();
    }
    if (threadIdx.x == 0) g_partial[blockIdx.x] = red[0];
}

__global__ void final_kernel(float* out) {
    if (threadIdx.x == 0) {
        float s = 0.f;
#pragma unroll
        for (int b = 0; b < 32; b++) s += g_partial[b];
        out[0] = s / (float)N_SAMPLES;
    }
}

// ---------------------------------------------------------------------------
extern "C" void kernel_launch(void* const* d_in, const int* in_sizes, int n_in,
                              void* d_out, int out_size) {
    const float* F = (const float*)d_in[0];
    const int* Lraw = (const int*)d_in[1];
    float* out = (float*)d_out;

    const int smem_bytes = SMEM_FLOATS * 4;   // 24KB -> 4 CTAs/SM
    cudaFuncSetAttribute(dist_kernel,
                         cudaFuncAttributeMaxDynamicSharedMemorySize, smem_bytes);

    conv_labels_kernel<<<1, 256>>>(Lraw);
    sort_kernel<<<1, 256>>>();
    gatherT_kernel<<<N_SAMPLES / 32, 256>>>(F);
    zeroS_kernel<<<NCLUST * N_SAMPLES / 1024, 1024>>>();
    dist_kernel<<<NPAIRS, 256, smem_bytes>>>();
    score_kernel<<<N_SAMPLES / 256, 256>>>();
    final_kernel<<<1, 32>>>(out);
}

// round 15
// speedup vs baseline: 1.3142x; 1.0885x over previous
#include <cuda_runtime.h>
#include <math.h>
#include <float.h>
#include <stdint.h>

#define N_SAMPLES 8192
#define DIM 128
#define NCLUST 64
#define TILE_I 128
#define TILE_J 64
#define NTJ (N_SAMPLES / TILE_J)    // 128
#define NPAIRS 4160
#define KS 16
#define NSLAB (DIM / KS)            // 8

// smem (floats): 3 A slabs (16x128=2048) + 3 B slabs (16x64=1024)
#define AS(b) ((b) * 2048)
#define BS(b) (6144 + (b) * 1024)
#define SMEM_FLOATS 9216            // 36KB -> 4 CTAs/SM (144KB)

typedef unsigned long long ull;
__device__ int   g_lab[N_SAMPLES];
__device__ int   g_labS[N_SAMPLES];
__device__ int   g_perm[N_SAMPLES];
__device__ float g_sqS[N_SAMPLES];
__device__ float g_FpT[DIM * N_SAMPLES];    // sorted, k-major
__device__ int   g_counts[NCLUST];
__device__ float g_S[NCLUST * N_SAMPLES];
__device__ float g_partial[256];

__device__ __forceinline__ void fma2(ull& acc, ull a, ull b) {
    asm("fma.rn.f32x2 %0, %1, %2, %0;" : "+l"(acc) : "l"(a), "l"(b));
}
__device__ __forceinline__ ull dup2(float a) {
    ull r;
    asm("mov.b64 %0, {%1, %1};" : "=l"(r) : "f"(a));
    return r;
}
__device__ __forceinline__ uint32_t smem_u32(const void* p) {
    uint32_t a;
    asm("{ .reg .u64 t; cvta.to.shared.u64 t, %1; cvt.u32.u64 %0, t; }"
        : "=r"(a) : "l"(p));
    return a;
}
__device__ __forceinline__ void cp16(uint32_t dst, const void* src) {
    asm volatile("cp.async.cg.shared.global [%0], [%1], 16;"
                 :: "r"(dst), "l"(src) : "memory");
}
#define CP_COMMIT() asm volatile("cp.async.commit_group;" ::: "memory")
#define CP_WAIT1()  asm volatile("cp.async.wait_group 1;" ::: "memory")
#define CP_WAIT0()  asm volatile("cp.async.wait_group 0;" ::: "memory")

// ---------------------------------------------------------------------------
__global__ void conv_labels_kernel(const int* __restrict__ Lraw) {
    __shared__ int is64;
    if (threadIdx.x == 0) {
        int odd_or = 0, even_bad = 0;
        for (int k = 0; k < 256; k += 2) {
            odd_or   |= Lraw[k + 1];
            even_bad |= ((unsigned)Lraw[k] >= NCLUST);
        }
        is64 = (odd_or == 0 && !even_bad) ? 1 : 0;
    }
    __syncthreads();
    const int w = is64;
    for (int i = threadIdx.x; i < N_SAMPLES; i += blockDim.x) {
        int v = w ? Lraw[2 * i] : Lraw[i];
        g_lab[i] = min(max(v, 0), NCLUST - 1);
    }
}

__global__ void sort_kernel() {
    __shared__ unsigned short T[256][NCLUST];
    __shared__ int colTot[NCLUST];
    __shared__ int cbase[NCLUST];
    const int s = threadIdx.x;
#pragma unroll
    for (int c = 0; c < NCLUST; c++) T[s][c] = 0;
    const int e0 = s * 32;
    for (int e = 0; e < 32; e++) T[s][g_lab[e0 + e]]++;
    __syncthreads();
    if (s < NCLUST) {
        int tot = 0;
        for (int q = 0; q < 256; q++) tot += T[q][s];
        colTot[s] = tot;
        g_counts[s] = tot;
    }
    __syncthreads();
    if (s == 0) {
        int run = 0;
        for (int c = 0; c < NCLUST; c++) { cbase[c] = run; run += colTot[c]; }
    }
    __syncthreads();
    if (s < NCLUST) {
        int run = cbase[s];
        for (int q = 0; q < 256; q++) {
            int w = T[q][s];
            T[q][s] = (unsigned short)run;
            run += w;
        }
    }
    __syncthreads();
    for (int e = 0; e < 32; e++) {
        int idx = e0 + e;
        int c = g_lab[idx];
        int p = T[s][c]++;
        g_perm[p] = idx;
        g_labS[p] = c;
    }
}

// Gather + transpose + sq norms, with g_S zeroing fused in.
__global__ void gatherT_kernel(const float* __restrict__ F) {
    __shared__ float T[32][DIM + 1];
    const int tid = threadIdx.x;
    const int lane = tid & 31, w = tid >> 5;
    const int base = blockIdx.x * 32;

    // fused zero of g_S: 256 blocks x 256 threads x 8 = 524288 floats
    {
        float4 z = make_float4(0.f, 0.f, 0.f, 0.f);
        float4* dst = reinterpret_cast<float4*>(g_S) +
                      (size_t)blockIdx.x * 512 + tid * 2;
        dst[0] = z;
        dst[1] = z;
    }

#pragma unroll
    for (int rr = 0; rr < 4; rr++) {
        const int p = base + w * 4 + rr;
        const int src = g_perm[p];
        float4 v = reinterpret_cast<const float4*>(F)[src * 32 + lane];
        T[w * 4 + rr][lane * 4 + 0] = v.x;
        T[w * 4 + rr][lane * 4 + 1] = v.y;
        T[w * 4 + rr][lane * 4 + 2] = v.z;
        T[w * 4 + rr][lane * 4 + 3] = v.w;
        float s = v.x * v.x + v.y * v.y + v.z * v.z + v.w * v.w;
#pragma unroll
        for (int o = 16; o > 0; o >>= 1) s += __shfl_down_sync(0xffffffffu, s, o);
        if (lane == 0) g_sqS[p] = s;
    }
    __syncthreads();
    const int i = tid & 31, ksub = tid >> 5;
#pragma unroll
    for (int step = 0; step < 16; step++) {
        int k = step * 8 + ksub;
        g_FpT[(size_t)k * N_SAMPLES + base + i] = T[i][k];
    }
}

// ---------------------------------------------------------------------------
// dist: 128x64 half-tile per CTA, jh >= 2*it. 8x4 reg tiles, FFMA2,
// TRIPLE-buffered cp.async slabs -> ONE __syncthreads per slab.
__global__ __launch_bounds__(256, 4) void dist_kernel() {
    int it = 0, rem = blockIdx.x, cnt = NTJ;
    while (rem >= cnt) { rem -= cnt; cnt -= 2; it++; }
    const int jh = 2 * it + rem;
    const bool diagLike = (rem < 2);

    extern __shared__ __align__(16) float smem[];
    const uint32_t sb = smem_u32(smem);
    const int tid = threadIdx.x;
    const int tx = tid & 15, ty = tid >> 4;
    const int iBase = it * TILE_I;
    const int jBase = jh * TILE_J;

#define ISSUE_SLAB(u)                                                         \
    {                                                                         \
        const int _b = (u) % 3;                                               \
        const float* srcA = g_FpT + (size_t)((u) * KS) * N_SAMPLES + iBase;   \
        const float* srcB = g_FpT + (size_t)((u) * KS) * N_SAMPLES + jBase;   \
        const uint32_t dA = sb + AS(_b) * 4;                                  \
        const uint32_t dB = sb + BS(_b) * 4;                                  \
        _Pragma("unroll")                                                     \
        for (int rr = 0; rr < 2; rr++) {                                      \
            int c = tid + rr * 256;                                           \
            int kk = c >> 5, off = (c & 31) * 4;                              \
            cp16(dA + (uint32_t)(kk * TILE_I + off) * 4,                      \
                 srcA + (size_t)kk * N_SAMPLES + off);                        \
        }                                                                     \
        {                                                                     \
            int kk = tid >> 4, off = (tid & 15) * 4;                          \
            cp16(dB + (uint32_t)(kk * TILE_J + off) * 4,                      \
                 srcB + (size_t)kk * N_SAMPLES + off);                        \
        }                                                                     \
        CP_COMMIT();                                                          \
    }

    ull acc[16];
#pragma unroll
    for (int z = 0; z < 16; z++) acc[z] = 0ull;

    ISSUE_SLAB(0);
    ISSUE_SLAB(1);

#pragma unroll 1
    for (int u = 0; u < NSLAB; u++) {
        if (u + 1 < NSLAB) CP_WAIT1(); else CP_WAIT0();
        __syncthreads();                 // slab u visible; buf (u+2)%3 free

        if (u + 2 < NSLAB) ISSUE_SLAB(u + 2);

        const int b = u % 3;
        const float* Ab = smem + AS(b) + ty * 8;
        const float* bp = smem + BS(b) + tx * 4;
#pragma unroll
        for (int k = 0; k < KS; k++) {
            float4 aLo = *reinterpret_cast<const float4*>(Ab + k * TILE_I);
            float4 aHi = *reinterpret_cast<const float4*>(Ab + k * TILE_I + 4);
            ull b0, b1;
            asm("ld.shared.v2.u64 {%0, %1}, [%2];"
                : "=l"(b0), "=l"(b1) : "l"(bp + k * TILE_J));
            ull a;
            a = dup2(aLo.x); fma2(acc[0],  a, b0); fma2(acc[1],  a, b1);
            a = dup2(aLo.y); fma2(acc[2],  a, b0); fma2(acc[3],  a, b1);
            a = dup2(aLo.z); fma2(acc[4],  a, b0); fma2(acc[5],  a, b1);
            a = dup2(aLo.w); fma2(acc[6],  a, b0); fma2(acc[7],  a, b1);
            a = dup2(aHi.x); fma2(acc[8],  a, b0); fma2(acc[9],  a, b1);
            a = dup2(aHi.y); fma2(acc[10], a, b0); fma2(acc[11], a, b1);
            a = dup2(aHi.z); fma2(acc[12], a, b0); fma2(acc[13], a, b1);
            a = dup2(aHi.w); fma2(acc[14], a, b0); fma2(acc[15], a, b1);
        }
    }
#undef ISSUE_SLAB

    // ---- epilogue: dots -> distances -> run-length atomics into g_S ----
    float isq[8];
    int   ilr[8];
#pragma unroll
    for (int ii = 0; ii < 8; ii++) {
        const int gi = iBase + ty * 8 + ii;
        isq[ii] = g_sqS[gi];
        ilr[ii] = g_labS[gi];
    }
    int   jlr[4];
    float jsr[4];
#pragma unroll
    for (int jj = 0; jj < 4; jj++) {
        const int gj = jBase + tx * 4 + jj;
        jlr[jj] = g_labS[gj];
        jsr[jj] = g_sqS[gj];
    }

#pragma unroll
    for (int q = 0; q < 16; q++) {
        const int ii = q >> 1, jp = q & 1;
        ull a2 = acc[q];
        float lo = __uint_as_float((unsigned)(a2 & 0xffffffffull));
        float hi = __uint_as_float((unsigned)(a2 >> 32));
        const int gi = iBase + ty * 8 + ii;
        const int gj = jBase + tx * 4 + jp * 2;
        float d2lo = isq[ii] + jsr[jp * 2]     - 2.f * lo;
        float d2hi = isq[ii] + jsr[jp * 2 + 1] - 2.f * hi;
        float dlo = 0.f, dhi = 0.f;
        if (d2lo > 0.f && gi != gj)
            asm("sqrt.approx.f32 %0, %1;" : "=f"(dlo) : "f"(d2lo));
        if (d2hi > 0.f && gi != gj + 1)
            asm("sqrt.approx.f32 %0, %1;" : "=f"(dhi) : "f"(d2hi));
        asm("mov.b64 %0, {%1, %2};" : "=l"(acc[q]) : "f"(dlo), "f"(dhi));
    }

    // i-side: rows gi accumulate over j grouped by sorted j-label
    {
        float run[8];
#pragma unroll
        for (int ii = 0; ii < 8; ii++) run[ii] = 0.f;
        int cur = jlr[0];
#pragma unroll
        for (int jj = 0; jj < 4; jj++) {
            const int c = jlr[jj];
            if (c != cur) {
#pragma unroll
                for (int ii = 0; ii < 8; ii++) {
                    atomicAdd(&g_S[(size_t)cur * N_SAMPLES + iBase + ty * 8 + ii],
                              run[ii]);
                    run[ii] = 0.f;
                }
                cur = c;
            }
            const int jp = jj >> 1;
#pragma unroll
            for (int ii = 0; ii < 8; ii++) {
                ull a2 = acc[ii * 2 + jp];
                float d = (jj & 1) ? __uint_as_float((unsigned)(a2 >> 32))
                                   : __uint_as_float((unsigned)(a2 & 0xffffffffull));
                run[ii] += d;
            }
        }
#pragma unroll
        for (int ii = 0; ii < 8; ii++)
            atomicAdd(&g_S[(size_t)cur * N_SAMPLES + iBase + ty * 8 + ii],
                      run[ii]);
    }

    // j-side (off-diag only): cols gj accumulate over i grouped by i-label
    if (!diagLike) {
        float run[4];
#pragma unroll
        for (int jj = 0; jj < 4; jj++) run[jj] = 0.f;
        int cur = ilr[0];
#pragma unroll
        for (int ii = 0; ii < 8; ii++) {
            const int c = ilr[ii];
            if (c != cur) {
#pragma unroll
                for (int jj = 0; jj < 4; jj++) {
                    atomicAdd(&g_S[(size_t)cur * N_SAMPLES + jBase + tx * 4 + jj],
                              run[jj]);
                    run[jj] = 0.f;
                }
                cur = c;
            }
#pragma unroll
            for (int jj = 0; jj < 4; jj++) {
                ull a2 = acc[ii * 2 + (jj >> 1)];
                float d = (jj & 1) ? __uint_as_float((unsigned)(a2 >> 32))
                                   : __uint_as_float((unsigned)(a2 & 0xffffffffull));
                run[jj] += d;
            }
        }
#pragma unroll
        for (int jj = 0; jj < 4; jj++)
            atomicAdd(&g_S[(size_t)cur * N_SAMPLES + jBase + tx * 4 + jj],
                      run[jj]);
    }
}

// ---------------------------------------------------------------------------
// score: 8 threads per sample (8 clusters each), shfl segment-reduce.
__global__ void score_kernel() {
    const int tid = threadIdx.x;
    const int sub = tid & 7;                      // cluster slice
    const int i = blockIdx.x * 32 + (tid >> 3);   // sample
    __shared__ int scounts[NCLUST];
    if (tid < NCLUST) scounts[tid] = g_counts[tid];
    __syncthreads();

    const int own = g_labS[i];
    float Sown = 0.f, b = FLT_MAX;
#pragma unroll
    for (int q = 0; q < 8; q++) {
        const int c = sub * 8 + q;
        float s = g_S[(size_t)c * N_SAMPLES + i];
        int cnt = scounts[c];
        if (c == own) Sown = s;
        else if (cnt > 0) b = fminf(b, s / (float)cnt);
    }
    // reduce across 8 lanes of this sample (contiguous lanes)
#pragma unroll
    for (int o = 4; o > 0; o >>= 1) {
        b = fminf(b, __shfl_xor_sync(0xffffffffu, b, o));
        Sown += __shfl_xor_sync(0xffffffffu, Sown, o);
    }

    __shared__ float red[32];
    if (sub == 0) {
        const int ocnt = scounts[own];
        const float a = Sown / fmaxf((float)ocnt - 1.f, 1.f);
        float score = 0.f;
        if (ocnt > 1) score = (b - a) / fmaxf(b, a);
        red[tid >> 3] = score;
    }
    __syncthreads();
    if (tid < 32) {
        float v = red[tid];
#pragma unroll
        for (int o = 16; o > 0; o >>= 1)
            v += __shfl_down_sync(0xffffffffu, v, o);
        if (tid == 0) g_partial[blockIdx.x] = v;
    }
}

__global__ void final_kernel(float* out) {
    const int lane = threadIdx.x;
    float s = 0.f;
#pragma unroll
    for (int b = 0; b < 8; b++) s += g_partial[lane * 8 + b];
#pragma unroll
    for (int o = 16; o > 0; o >>= 1) s += __shfl_down_sync(0xffffffffu, s, o);
    if (lane == 0) out[0] = s / (float)N_SAMPLES;
}

// ---------------------------------------------------------------------------
extern "C" void kernel_launch(void* const* d_in, const int* in_sizes, int n_in,
                              void* d_out, int out_size) {
    const float* F = (const float*)d_in[0];
    const int* Lraw = (const int*)d_in[1];
    float* out = (float*)d_out;

    const int smem_bytes = SMEM_FLOATS * 4;   // 36KB -> 4 CTAs/SM
    cudaFuncSetAttribute(dist_kernel,
                         cudaFuncAttributeMaxDynamicSharedMemorySize, smem_bytes);

    conv_labels_kernel<<<1, 256>>>(Lraw);
    sort_kernel<<<1, 256>>>();
    gatherT_kernel<<<N_SAMPLES / 32, 256>>>(F);
    dist_kernel<<<NPAIRS, 256, smem_bytes>>>();
    score_kernel<<<N_SAMPLES / 32, 256>>>();
    final_kernel<<<1, 32>>>(out);
}

// round 16
// speedup vs baseline: 1.3496x; 1.0270x over previous
#include <cuda_runtime.h>
#include <math.h>
#include <float.h>
#include <stdint.h>

#define N_SAMPLES 8192
#define DIM 128
#define NCLUST 64
#define TILE_I 128
#define TILE_J 64
#define NTJ (N_SAMPLES / TILE_J)    // 128
#define NPAIRS 4160
#define KS 16
#define NSLAB (DIM / KS)            // 8

// smem (floats): 3 A slabs (16x128=2048) + 3 B slabs (16x64=1024)
#define AS(b) ((b) * 2048)
#define BS(b) (6144 + (b) * 1024)
#define SMEM_FLOATS 9216            // 36KB -> 4 CTAs/SM (144KB)

typedef unsigned long long ull;
__device__ int   g_lab[N_SAMPLES];
__device__ int   g_labS[N_SAMPLES];
__device__ int   g_perm[N_SAMPLES];
__device__ float g_sqS[N_SAMPLES];
__device__ float g_FpT[DIM * N_SAMPLES];    // sorted, k-major
__device__ int   g_counts[NCLUST];
__device__ float g_S[NCLUST * N_SAMPLES];
__device__ float g_partial[256];

__device__ __forceinline__ void fma2(ull& acc, ull a, ull b) {
    asm("fma.rn.f32x2 %0, %1, %2, %0;" : "+l"(acc) : "l"(a), "l"(b));
}
__device__ __forceinline__ ull dup2(float a) {
    ull r;
    asm("mov.b64 %0, {%1, %1};" : "=l"(r) : "f"(a));
    return r;
}
__device__ __forceinline__ uint32_t smem_u32(const void* p) {
    uint32_t a;
    asm("{ .reg .u64 t; cvta.to.shared.u64 t, %1; cvt.u32.u64 %0, t; }"
        : "=r"(a) : "l"(p));
    return a;
}
__device__ __forceinline__ void cp16(uint32_t dst, const void* src) {
    asm volatile("cp.async.cg.shared.global [%0], [%1], 16;"
                 :: "r"(dst), "l"(src) : "memory");
}
#define CP_COMMIT() asm volatile("cp.async.commit_group;" ::: "memory")
#define CP_WAIT1()  asm volatile("cp.async.wait_group 1;" ::: "memory")
#define CP_WAIT0()  asm volatile("cp.async.wait_group 0;" ::: "memory")

// ---------------------------------------------------------------------------
// Fused: label normalization (int32/int64 autodetect) + deterministic
// counting sort by label. Single block, 256 threads.
__global__ void sort_kernel(const int* __restrict__ Lraw) {
    __shared__ unsigned short T[256][NCLUST];
    __shared__ int colTot[NCLUST];
    __shared__ int cbase[NCLUST];
    __shared__ int is64;
    const int s = threadIdx.x;

    if (s == 0) {
        int odd_or = 0, even_bad = 0;
        for (int k = 0; k < 256; k += 2) {
            odd_or   |= Lraw[k + 1];
            even_bad |= ((unsigned)Lraw[k] >= NCLUST);
        }
        is64 = (odd_or == 0 && !even_bad) ? 1 : 0;
    }
    __syncthreads();
    const int w = is64;
    for (int i = s; i < N_SAMPLES; i += 256) {
        int v = w ? Lraw[2 * i] : Lraw[i];
        g_lab[i] = min(max(v, 0), NCLUST - 1);
    }
    __syncthreads();

#pragma unroll
    for (int c = 0; c < NCLUST; c++) T[s][c] = 0;
    const int e0 = s * 32;
    for (int e = 0; e < 32; e++) T[s][g_lab[e0 + e]]++;
    __syncthreads();
    if (s < NCLUST) {
        int tot = 0;
        for (int q = 0; q < 256; q++) tot += T[q][s];
        colTot[s] = tot;
        g_counts[s] = tot;
    }
    __syncthreads();
    if (s == 0) {
        int run = 0;
        for (int c = 0; c < NCLUST; c++) { cbase[c] = run; run += colTot[c]; }
    }
    __syncthreads();
    if (s < NCLUST) {
        int run = cbase[s];
        for (int q = 0; q < 256; q++) {
            int w2 = T[q][s];
            T[q][s] = (unsigned short)run;
            run += w2;
        }
    }
    __syncthreads();
    for (int e = 0; e < 32; e++) {
        int idx = e0 + e;
        int c = g_lab[idx];
        int p = T[s][c]++;
        g_perm[p] = idx;
        g_labS[p] = c;
    }
}

// Gather + transpose + sq norms, with g_S zeroing fused in.
__global__ void gatherT_kernel(const float* __restrict__ F) {
    __shared__ float T[32][DIM + 1];
    const int tid = threadIdx.x;
    const int lane = tid & 31, w = tid >> 5;
    const int base = blockIdx.x * 32;

    {
        float4 z = make_float4(0.f, 0.f, 0.f, 0.f);
        float4* dst = reinterpret_cast<float4*>(g_S) +
                      (size_t)blockIdx.x * 512 + tid * 2;
        dst[0] = z;
        dst[1] = z;
    }

#pragma unroll
    for (int rr = 0; rr < 4; rr++) {
        const int p = base + w * 4 + rr;
        const int src = g_perm[p];
        float4 v = reinterpret_cast<const float4*>(F)[src * 32 + lane];
        T[w * 4 + rr][lane * 4 + 0] = v.x;
        T[w * 4 + rr][lane * 4 + 1] = v.y;
        T[w * 4 + rr][lane * 4 + 2] = v.z;
        T[w * 4 + rr][lane * 4 + 3] = v.w;
        float s = v.x * v.x + v.y * v.y + v.z * v.z + v.w * v.w;
#pragma unroll
        for (int o = 16; o > 0; o >>= 1) s += __shfl_down_sync(0xffffffffu, s, o);
        if (lane == 0) g_sqS[p] = s;
    }
    __syncthreads();
    const int i = tid & 31, ksub = tid >> 5;
#pragma unroll
    for (int step = 0; step < 16; step++) {
        int k = step * 8 + ksub;
        g_FpT[(size_t)k * N_SAMPLES + base + i] = T[i][k];
    }
}

// ---------------------------------------------------------------------------
// dist: 128x64 half-tile per CTA, jh >= 2*it. Thread computes 8i x 4j with
// i-PAIR accumulators: A loads as packed pairs (no MOV), B duplicated (4 MOVs).
// Triple-buffered cp.async slabs, one barrier per slab, global atomics epilogue.
__global__ __launch_bounds__(256, 4) void dist_kernel() {
    int it = 0, rem = blockIdx.x, cnt = NTJ;
    while (rem >= cnt) { rem -= cnt; cnt -= 2; it++; }
    const int jh = 2 * it + rem;
    const bool diagLike = (rem < 2);

    extern __shared__ __align__(16) float smem[];
    const uint32_t sb = smem_u32(smem);
    const int tid = threadIdx.x;
    const int tx = tid & 15, ty = tid >> 4;
    const int iBase = it * TILE_I;
    const int jBase = jh * TILE_J;

#define ISSUE_SLAB(u)                                                         \
    {                                                                         \
        const int _b = (u) % 3;                                               \
        const float* srcA = g_FpT + (size_t)((u) * KS) * N_SAMPLES + iBase;   \
        const float* srcB = g_FpT + (size_t)((u) * KS) * N_SAMPLES + jBase;   \
        const uint32_t dA = sb + AS(_b) * 4;                                  \
        const uint32_t dB = sb + BS(_b) * 4;                                  \
        _Pragma("unroll")                                                     \
        for (int rr = 0; rr < 2; rr++) {                                      \
            int c = tid + rr * 256;                                           \
            int kk = c >> 5, off = (c & 31) * 4;                              \
            cp16(dA + (uint32_t)(kk * TILE_I + off) * 4,                      \
                 srcA + (size_t)kk * N_SAMPLES + off);                        \
        }                                                                     \
        {                                                                     \
            int kk = tid >> 4, off = (tid & 15) * 4;                          \
            cp16(dB + (uint32_t)(kk * TILE_J + off) * 4,                      \
                 srcB + (size_t)kk * N_SAMPLES + off);                        \
        }                                                                     \
        CP_COMMIT();                                                          \
    }

    // acc[ip*4 + jj]: lo lane = i=2ip, hi lane = i=2ip+1, column jj
    ull acc[16];
#pragma unroll
    for (int z = 0; z < 16; z++) acc[z] = 0ull;

    ISSUE_SLAB(0);
    ISSUE_SLAB(1);

#pragma unroll 1
    for (int u = 0; u < NSLAB; u++) {
        if (u + 1 < NSLAB) CP_WAIT1(); else CP_WAIT0();
        __syncthreads();

        if (u + 2 < NSLAB) ISSUE_SLAB(u + 2);

        const int b = u % 3;
        const float* Ab = smem + AS(b) + ty * 8;
        const float* bp = smem + BS(b) + tx * 4;
#pragma unroll
        for (int k = 0; k < KS; k++) {
            ull a0, a1, a2, a3;
            asm("ld.shared.v2.u64 {%0, %1}, [%2];"
                : "=l"(a0), "=l"(a1) : "l"(Ab + k * TILE_I));
            asm("ld.shared.v2.u64 {%0, %1}, [%2];"
                : "=l"(a2), "=l"(a3) : "l"(Ab + k * TILE_I + 4));
            float4 bv = *reinterpret_cast<const float4*>(bp + k * TILE_J);
            ull b0 = dup2(bv.x), b1 = dup2(bv.y), b2 = dup2(bv.z), b3 = dup2(bv.w);
            fma2(acc[0],  a0, b0); fma2(acc[1],  a0, b1);
            fma2(acc[2],  a0, b2); fma2(acc[3],  a0, b3);
            fma2(acc[4],  a1, b0); fma2(acc[5],  a1, b1);
            fma2(acc[6],  a1, b2); fma2(acc[7],  a1, b3);
            fma2(acc[8],  a2, b0); fma2(acc[9],  a2, b1);
            fma2(acc[10], a2, b2); fma2(acc[11], a2, b3);
            fma2(acc[12], a3, b0); fma2(acc[13], a3, b1);
            fma2(acc[14], a3, b2); fma2(acc[15], a3, b3);
        }
    }
#undef ISSUE_SLAB

    // ---- epilogue: dots -> distances -> run-length atomics into g_S ----
    float isq[8];
    int   ilr[8];
#pragma unroll
    for (int ii = 0; ii < 8; ii++) {
        const int gi = iBase + ty * 8 + ii;
        isq[ii] = g_sqS[gi];
        ilr[ii] = g_labS[gi];
    }
    int   jlr[4];
    float jsr[4];
#pragma unroll
    for (int jj = 0; jj < 4; jj++) {
        const int gj = jBase + tx * 4 + jj;
        jlr[jj] = g_labS[gj];
        jsr[jj] = g_sqS[gj];
    }

    // convert: acc[ip*4+jj] lo = (i=2ip, j=jj), hi = (i=2ip+1, j=jj)
#pragma unroll
    for (int q = 0; q < 16; q++) {
        const int ip = q >> 2, jj = q & 3;
        ull a2 = acc[q];
        float lo = __uint_as_float((unsigned)(a2 & 0xffffffffull));
        float hi = __uint_as_float((unsigned)(a2 >> 32));
        const int gi = iBase + ty * 8 + 2 * ip;
        const int gj = jBase + tx * 4 + jj;
        float d2lo = isq[2 * ip]     + jsr[jj] - 2.f * lo;
        float d2hi = isq[2 * ip + 1] + jsr[jj] - 2.f * hi;
        float dlo = 0.f, dhi = 0.f;
        if (d2lo > 0.f && gi != gj)
            asm("sqrt.approx.f32 %0, %1;" : "=f"(dlo) : "f"(d2lo));
        if (d2hi > 0.f && (gi + 1) != gj)
            asm("sqrt.approx.f32 %0, %1;" : "=f"(dhi) : "f"(d2hi));
        asm("mov.b64 %0, {%1, %2};" : "=l"(acc[q]) : "f"(dlo), "f"(dhi));
    }

    // i-side: rows accumulate over j grouped by sorted j-label
    {
        float run[8];
#pragma unroll
        for (int ii = 0; ii < 8; ii++) run[ii] = 0.f;
        int cur = jlr[0];
#pragma unroll
        for (int jj = 0; jj < 4; jj++) {
            const int c = jlr[jj];
            if (c != cur) {
#pragma unroll
                for (int ii = 0; ii < 8; ii++) {
                    atomicAdd(&g_S[(size_t)cur * N_SAMPLES + iBase + ty * 8 + ii],
                              run[ii]);
                    run[ii] = 0.f;
                }
                cur = c;
            }
#pragma unroll
            for (int ii = 0; ii < 8; ii++) {
                ull a2 = acc[(ii >> 1) * 4 + jj];
                float d = (ii & 1) ? __uint_as_float((unsigned)(a2 >> 32))
                                   : __uint_as_float((unsigned)(a2 & 0xffffffffull));
                run[ii] += d;
            }
        }
#pragma unroll
        for (int ii = 0; ii < 8; ii++)
            atomicAdd(&g_S[(size_t)cur * N_SAMPLES + iBase + ty * 8 + ii],
                      run[ii]);
    }

    // j-side (off-diag only): cols accumulate over i grouped by i-label
    if (!diagLike) {
        float run[4];
#pragma unroll
        for (int jj = 0; jj < 4; jj++) run[jj] = 0.f;
        int cur = ilr[0];
#pragma unroll
        for (int ii = 0; ii < 8; ii++) {
            const int c = ilr[ii];
            if (c != cur) {
#pragma unroll
                for (int jj = 0; jj < 4; jj++) {
                    atomicAdd(&g_S[(size_t)cur * N_SAMPLES + jBase + tx * 4 + jj],
                              run[jj]);
                    run[jj] = 0.f;
                }
                cur = c;
            }
#pragma unroll
            for (int jj = 0; jj < 4; jj++) {
                ull a2 = acc[(ii >> 1) * 4 + jj];
                float d = (ii & 1) ? __uint_as_float((unsigned)(a2 >> 32))
                                   : __uint_as_float((unsigned)(a2 & 0xffffffffull));
                run[jj] += d;
            }
        }
#pragma unroll
        for (int jj = 0; jj < 4; jj++)
            atomicAdd(&g_S[(size_t)cur * N_SAMPLES + jBase + tx * 4 + jj],
                      run[jj]);
    }
}

// ---------------------------------------------------------------------------
// score: 8 threads per sample (8 clusters each), shfl segment-reduce.
__global__ void score_kernel() {
    const int tid = threadIdx.x;
    const int sub = tid & 7;
    const int i = blockIdx.x * 32 + (tid >> 3);
    __shared__ int scounts[NCLUST];
    if (tid < NCLUST) scounts[tid] = g_counts[tid];
    __syncthreads();

    const int own = g_labS[i];
    float Sown = 0.f, b = FLT_MAX;
#pragma unroll
    for (int q = 0; q < 8; q++) {
        const int c = sub * 8 + q;
        float s = g_S[(size_t)c * N_SAMPLES + i];
        int cnt = scounts[c];
        if (c == own) Sown = s;
        else if (cnt > 0) b = fminf(b, s / (float)cnt);
    }
#pragma unroll
    for (int o = 4; o > 0; o >>= 1) {
        b = fminf(b, __shfl_xor_sync(0xffffffffu, b, o));
        Sown += __shfl_xor_sync(0xffffffffu, Sown, o);
    }

    __shared__ float red[32];
    if (sub == 0) {
        const int ocnt = scounts[own];
        const float a = Sown / fmaxf((float)ocnt - 1.f, 1.f);
        float score = 0.f;
        if (ocnt > 1) score = (b - a) / fmaxf(b, a);
        red[tid >> 3] = score;
    }
    __syncthreads();
    if (tid < 32) {
        float v = red[tid];
#pragma unroll
        for (int o = 16; o > 0; o >>= 1)
            v += __shfl_down_sync(0xffffffffu, v, o);
        if (tid == 0) g_partial[blockIdx.x] = v;
    }
}

__global__ void final_kernel(float* out) {
    const int lane = threadIdx.x;
    float s = 0.f;
#pragma unroll
    for (int b = 0; b < 8; b++) s += g_partial[lane * 8 + b];
#pragma unroll
    for (int o = 16; o > 0; o >>= 1) s += __shfl_down_sync(0xffffffffu, s, o);
    if (lane == 0) out[0] = s / (float)N_SAMPLES;
}

// ---------------------------------------------------------------------------
extern "C" void kernel_launch(void* const* d_in, const int* in_sizes, int n_in,
                              void* d_out, int out_size) {
    const float* F = (const float*)d_in[0];
    const int* Lraw = (const int*)d_in[1];
    float* out = (float*)d_out;

    const int smem_bytes = SMEM_FLOATS * 4;   // 36KB -> 4 CTAs/SM
    cudaFuncSetAttribute(dist_kernel,
                         cudaFuncAttributeMaxDynamicSharedMemorySize, smem_bytes);

    sort_kernel<<<1, 256>>>(Lraw);
    gatherT_kernel<<<N_SAMPLES / 32, 256>>>(F);
    dist_kernel<<<NPAIRS, 256, smem_bytes>>>();
    score_kernel<<<N_SAMPLES / 32, 256>>>();
    final_kernel<<<1, 32>>>(out);
}

// round 17
// speedup vs baseline: 1.3581x; 1.0063x over previous
#include <cuda_runtime.h>
#include <math.h>
#include <float.h>
#include <stdint.h>

#define N_SAMPLES 8192
#define DIM 128
#define NCLUST 64
#define TILE_I 128
#define TILE_J 64
#define NTJ (N_SAMPLES / TILE_J)    // 128
#define NPAIRS 4160
#define KS 16
#define NSLAB (DIM / KS)            // 8

// smem (floats): 3 A slabs (16x128=2048) + 3 B slabs (16x64=1024)
#define AS(b) ((b) * 2048)
#define BS(b) (6144 + (b) * 1024)
#define SMEM_FLOATS 9216            // 36KB -> 4 CTAs/SM (144KB)

typedef unsigned long long ull;
__device__ int   g_lab[N_SAMPLES];
__device__ int   g_labS[N_SAMPLES];
__device__ int   g_perm[N_SAMPLES];
__device__ float g_sqS[N_SAMPLES];
__device__ float g_FpT[DIM * N_SAMPLES];    // sorted, k-major
__device__ int   g_counts[NCLUST];
__device__ float g_S[NCLUST * N_SAMPLES];
__device__ float g_partial[512];

__device__ __forceinline__ void fma2(ull& acc, ull a, ull b) {
    asm("fma.rn.f32x2 %0, %1, %2, %0;" : "+l"(acc) : "l"(a), "l"(b));
}
__device__ __forceinline__ ull dup2(float a) {
    ull r;
    asm("mov.b64 %0, {%1, %1};" : "=l"(r) : "f"(a));
    return r;
}
__device__ __forceinline__ uint32_t smem_u32(const void* p) {
    uint32_t a;
    asm("{ .reg .u64 t; cvta.to.shared.u64 t, %1; cvt.u32.u64 %0, t; }"
        : "=r"(a) : "l"(p));
    return a;
}
__device__ __forceinline__ void cp16(uint32_t dst, const void* src) {
    asm volatile("cp.async.cg.shared.global [%0], [%1], 16;"
                 :: "r"(dst), "l"(src) : "memory");
}
__device__ __forceinline__ void prefetchL2(const void* p) {
    asm volatile("prefetch.global.L2 [%0];" :: "l"(p));
}
#define CP_COMMIT() asm volatile("cp.async.commit_group;" ::: "memory")
#define CP_WAIT1()  asm volatile("cp.async.wait_group 1;" ::: "memory")
#define CP_WAIT0()  asm volatile("cp.async.wait_group 0;" ::: "memory")

// ---------------------------------------------------------------------------
// Fused: label normalization (int32/int64 autodetect) + deterministic
// counting sort by label. Single block, 256 threads.
__global__ void sort_kernel(const int* __restrict__ Lraw) {
    __shared__ unsigned short T[256][NCLUST];
    __shared__ int colTot[NCLUST];
    __shared__ int cbase[NCLUST];
    __shared__ int is64;
    const int s = threadIdx.x;

    if (s == 0) {
        int odd_or = 0, even_bad = 0;
        for (int k = 0; k < 256; k += 2) {
            odd_or   |= Lraw[k + 1];
            even_bad |= ((unsigned)Lraw[k] >= NCLUST);
        }
        is64 = (odd_or == 0 && !even_bad) ? 1 : 0;
    }
    __syncthreads();
    const int w = is64;
    for (int i = s; i < N_SAMPLES; i += 256) {
        int v = w ? Lraw[2 * i] : Lraw[i];
        g_lab[i] = min(max(v, 0), NCLUST - 1);
    }
    __syncthreads();

#pragma unroll
    for (int c = 0; c < NCLUST; c++) T[s][c] = 0;
    const int e0 = s * 32;
    for (int e = 0; e < 32; e++) T[s][g_lab[e0 + e]]++;
    __syncthreads();
    if (s < NCLUST) {
        int tot = 0;
        for (int q = 0; q < 256; q++) tot += T[q][s];
        colTot[s] = tot;
        g_counts[s] = tot;
    }
    __syncthreads();
    if (s == 0) {
        int run = 0;
        for (int c = 0; c < NCLUST; c++) { cbase[c] = run; run += colTot[c]; }
    }
    __syncthreads();
    if (s < NCLUST) {
        int run = cbase[s];
        for (int q = 0; q < 256; q++) {
            int w2 = T[q][s];
            T[q][s] = (unsigned short)run;
            run += w2;
        }
    }
    __syncthreads();
    for (int e = 0; e < 32; e++) {
        int idx = e0 + e;
        int c = g_lab[idx];
        int p = T[s][c]++;
        g_perm[p] = idx;
        g_labS[p] = c;
    }
}

// Gather + transpose + sq norms, with g_S zeroing fused in.
__global__ void gatherT_kernel(const float* __restrict__ F) {
    __shared__ float T[32][DIM + 1];
    const int tid = threadIdx.x;
    const int lane = tid & 31, w = tid >> 5;
    const int base = blockIdx.x * 32;

    {
        float4 z = make_float4(0.f, 0.f, 0.f, 0.f);
        float4* dst = reinterpret_cast<float4*>(g_S) +
                      (size_t)blockIdx.x * 512 + tid * 2;
        dst[0] = z;
        dst[1] = z;
    }

#pragma unroll
    for (int rr = 0; rr < 4; rr++) {
        const int p = base + w * 4 + rr;
        const int src = g_perm[p];
        float4 v = reinterpret_cast<const float4*>(F)[src * 32 + lane];
        T[w * 4 + rr][lane * 4 + 0] = v.x;
        T[w * 4 + rr][lane * 4 + 1] = v.y;
        T[w * 4 + rr][lane * 4 + 2] = v.z;
        T[w * 4 + rr][lane * 4 + 3] = v.w;
        float s = v.x * v.x + v.y * v.y + v.z * v.z + v.w * v.w;
#pragma unroll
        for (int o = 16; o > 0; o >>= 1) s += __shfl_down_sync(0xffffffffu, s, o);
        if (lane == 0) g_sqS[p] = s;
    }
    __syncthreads();
    const int i = tid & 31, ksub = tid >> 5;
#pragma unroll
    for (int step = 0; step < 16; step++) {
        int k = step * 8 + ksub;
        g_FpT[(size_t)k * N_SAMPLES + base + i] = T[i][k];
    }
}

// ---------------------------------------------------------------------------
// dist: 128x64 half-tile per CTA, jh >= 2*it. Thread computes 8i x 4j with
// i-PAIR accumulators: A loads as packed pairs (no MOV), B duplicated (4 MOVs).
// Triple-buffered cp.async slabs, one barrier per slab, global atomics epilogue.
__global__ __launch_bounds__(256, 4) void dist_kernel() {
    int it = 0, rem = blockIdx.x, cnt = NTJ;
    while (rem >= cnt) { rem -= cnt; cnt -= 2; it++; }
    const int jh = 2 * it + rem;
    const bool diagLike = (rem < 2);

    extern __shared__ __align__(16) float smem[];
    const uint32_t sb = smem_u32(smem);
    const int tid = threadIdx.x;
    const int tx = tid & 15, ty = tid >> 4;
    const int iBase = it * TILE_I;
    const int jBase = jh * TILE_J;

    // warm L2/L1 for the epilogue metadata (no register cost)
    prefetchL2(&g_sqS[iBase + ty * 8]);
    prefetchL2(&g_labS[iBase + ty * 8]);
    prefetchL2(&g_sqS[jBase + tx * 4]);
    prefetchL2(&g_labS[jBase + tx * 4]);

#define ISSUE_SLAB(u)                                                         \
    {                                                                         \
        const int _b = (u) % 3;                                               \
        const float* srcA = g_FpT + (size_t)((u) * KS) * N_SAMPLES + iBase;   \
        const float* srcB = g_FpT + (size_t)((u) * KS) * N_SAMPLES + jBase;   \
        const uint32_t dA = sb + AS(_b) * 4;                                  \
        const uint32_t dB = sb + BS(_b) * 4;                                  \
        _Pragma("unroll")                                                     \
        for (int rr = 0; rr < 2; rr++) {                                      \
            int c = tid + rr * 256;                                           \
            int kk = c >> 5, off = (c & 31) * 4;                              \
            cp16(dA + (uint32_t)(kk * TILE_I + off) * 4,                      \
                 srcA + (size_t)kk * N_SAMPLES + off);                        \
        }                                                                     \
        {                                                                     \
            int kk = tid >> 4, off = (tid & 15) * 4;                          \
            cp16(dB + (uint32_t)(kk * TILE_J + off) * 4,                      \
                 srcB + (size_t)kk * N_SAMPLES + off);                        \
        }                                                                     \
        CP_COMMIT();                                                          \
    }

    // acc[ip*4 + jj]: lo lane = i=2ip, hi lane = i=2ip+1, column jj
    ull acc[16];
#pragma unroll
    for (int z = 0; z < 16; z++) acc[z] = 0ull;

    ISSUE_SLAB(0);
    ISSUE_SLAB(1);

#pragma unroll 1
    for (int u = 0; u < NSLAB; u++) {
        if (u + 1 < NSLAB) CP_WAIT1(); else CP_WAIT0();
        __syncthreads();

        if (u + 2 < NSLAB) ISSUE_SLAB(u + 2);

        const int b = u % 3;
        const float* Ab = smem + AS(b) + ty * 8;
        const float* bp = smem + BS(b) + tx * 4;
#pragma unroll
        for (int k = 0; k < KS; k++) {
            ull a0, a1, a2, a3;
            asm("ld.shared.v2.u64 {%0, %1}, [%2];"
                : "=l"(a0), "=l"(a1) : "l"(Ab + k * TILE_I));
            asm("ld.shared.v2.u64 {%0, %1}, [%2];"
                : "=l"(a2), "=l"(a3) : "l"(Ab + k * TILE_I + 4));
            float4 bv = *reinterpret_cast<const float4*>(bp + k * TILE_J);
            ull b0 = dup2(bv.x), b1 = dup2(bv.y), b2 = dup2(bv.z), b3 = dup2(bv.w);
            fma2(acc[0],  a0, b0); fma2(acc[1],  a0, b1);
            fma2(acc[2],  a0, b2); fma2(acc[3],  a0, b3);
            fma2(acc[4],  a1, b0); fma2(acc[5],  a1, b1);
            fma2(acc[6],  a1, b2); fma2(acc[7],  a1, b3);
            fma2(acc[8],  a2, b0); fma2(acc[9],  a2, b1);
            fma2(acc[10], a2, b2); fma2(acc[11], a2, b3);
            fma2(acc[12], a3, b0); fma2(acc[13], a3, b1);
            fma2(acc[14], a3, b2); fma2(acc[15], a3, b3);
        }
    }
#undef ISSUE_SLAB

    // ---- epilogue: dots -> distances -> run-length atomics into g_S ----
    float isq[8];
    int   ilr[8];
#pragma unroll
    for (int ii = 0; ii < 8; ii++) {
        const int gi = iBase + ty * 8 + ii;
        isq[ii] = g_sqS[gi];
        ilr[ii] = g_labS[gi];
    }
    int   jlr[4];
    float jsr[4];
#pragma unroll
    for (int jj = 0; jj < 4; jj++) {
        const int gj = jBase + tx * 4 + jj;
        jlr[jj] = g_labS[gj];
        jsr[jj] = g_sqS[gj];
    }

    // convert: acc[ip*4+jj] lo = (i=2ip, j=jj), hi = (i=2ip+1, j=jj)
#pragma unroll
    for (int q = 0; q < 16; q++) {
        const int ip = q >> 2, jj = q & 3;
        ull a2 = acc[q];
        float lo = __uint_as_float((unsigned)(a2 & 0xffffffffull));
        float hi = __uint_as_float((unsigned)(a2 >> 32));
        const int gi = iBase + ty * 8 + 2 * ip;
        const int gj = jBase + tx * 4 + jj;
        float d2lo = isq[2 * ip]     + jsr[jj] - 2.f * lo;
        float d2hi = isq[2 * ip + 1] + jsr[jj] - 2.f * hi;
        float dlo = 0.f, dhi = 0.f;
        if (d2lo > 0.f && gi != gj)
            asm("sqrt.approx.f32 %0, %1;" : "=f"(dlo) : "f"(d2lo));
        if (d2hi > 0.f && (gi + 1) != gj)
            asm("sqrt.approx.f32 %0, %1;" : "=f"(dhi) : "f"(d2hi));
        asm("mov.b64 %0, {%1, %2};" : "=l"(acc[q]) : "f"(dlo), "f"(dhi));
    }

    // i-side: rows accumulate over j grouped by sorted j-label
    {
        float run[8];
#pragma unroll
        for (int ii = 0; ii < 8; ii++) run[ii] = 0.f;
        int cur = jlr[0];
#pragma unroll
        for (int jj = 0; jj < 4; jj++) {
            const int c = jlr[jj];
            if (c != cur) {
#pragma unroll
                for (int ii = 0; ii < 8; ii++) {
                    atomicAdd(&g_S[(size_t)cur * N_SAMPLES + iBase + ty * 8 + ii],
                              run[ii]);
                    run[ii] = 0.f;
                }
                cur = c;
            }
#pragma unroll
            for (int ii = 0; ii < 8; ii++) {
                ull a2 = acc[(ii >> 1) * 4 + jj];
                float d = (ii & 1) ? __uint_as_float((unsigned)(a2 >> 32))
                                   : __uint_as_float((unsigned)(a2 & 0xffffffffull));
                run[ii] += d;
            }
        }
#pragma unroll
        for (int ii = 0; ii < 8; ii++)
            atomicAdd(&g_S[(size_t)cur * N_SAMPLES + iBase + ty * 8 + ii],
                      run[ii]);
    }

    // j-side (off-diag only): cols accumulate over i grouped by i-label
    if (!diagLike) {
        float run[4];
#pragma unroll
        for (int jj = 0; jj < 4; jj++) run[jj] = 0.f;
        int cur = ilr[0];
#pragma unroll
        for (int ii = 0; ii < 8; ii++) {
            const int c = ilr[ii];
            if (c != cur) {
#pragma unroll
                for (int jj = 0; jj < 4; jj++) {
                    atomicAdd(&g_S[(size_t)cur * N_SAMPLES + jBase + tx * 4 + jj],
                              run[jj]);
                    run[jj] = 0.f;
                }
                cur = c;
            }
#pragma unroll
            for (int jj = 0; jj < 4; jj++) {
                ull a2 = acc[(ii >> 1) * 4 + jj];
                float d = (ii & 1) ? __uint_as_float((unsigned)(a2 >> 32))
                                   : __uint_as_float((unsigned)(a2 & 0xffffffffull));
                run[jj] += d;
            }
        }
#pragma unroll
        for (int jj = 0; jj < 4; jj++)
            atomicAdd(&g_S[(size_t)cur * N_SAMPLES + jBase + tx * 4 + jj],
                      run[jj]);
    }
}

// ---------------------------------------------------------------------------
// score: 16 threads per sample (4 clusters each), shfl segment-reduce.
// 512 blocks x 256 threads = 131072 threads -> latency hidden.
__global__ void score_kernel() {
    const int tid = threadIdx.x;
    const int sub = tid & 15;                     // cluster slice (4 each)
    const int i = blockIdx.x * 16 + (tid >> 4);   // sample
    __shared__ int scounts[NCLUST];
    if (tid < NCLUST) scounts[tid] = g_counts[tid];
    __syncthreads();

    const int own = g_labS[i];
    float Sown = 0.f, b = FLT_MAX;
#pragma unroll
    for (int q = 0; q < 4; q++) {
        const int c = sub * 4 + q;
        float s = g_S[(size_t)c * N_SAMPLES + i];
        int cnt = scounts[c];
        if (c == own) Sown = s;
        else if (cnt > 0) b = fminf(b, s / (float)cnt);
    }
#pragma unroll
    for (int o = 8; o > 0; o >>= 1) {
        b = fminf(b, __shfl_xor_sync(0xffffffffu, b, o));
        Sown += __shfl_xor_sync(0xffffffffu, Sown, o);
    }

    __shared__ float red[16];
    if (sub == 0) {
        const int ocnt = scounts[own];
        const float a = Sown / fmaxf((float)ocnt - 1.f, 1.f);
        float score = 0.f;
        if (ocnt > 1) score = (b - a) / fmaxf(b, a);
        red[tid >> 4] = score;
    }
    __syncthreads();
    if (tid < 16) {
        float v = red[tid];
#pragma unroll
        for (int o = 8; o > 0; o >>= 1)
            v += __shfl_down_sync(0x0000ffffu, v, o);
        if (tid == 0) g_partial[blockIdx.x] = v;
    }
}

__global__ void final_kernel(float* out) {
    const int lane = threadIdx.x;
    float s = 0.f;
#pragma unroll
    for (int b = 0; b < 16; b++) s += g_partial[lane * 16 + b];
#pragma unroll
    for (int o = 16; o > 0; o >>= 1) s += __shfl_down_sync(0xffffffffu, s, o);
    if (lane == 0) out[0] = s / (float)N_SAMPLES;
}

// ---------------------------------------------------------------------------
extern "C" void kernel_launch(void* const* d_in, const int* in_sizes, int n_in,
                              void* d_out, int out_size) {
    const float* F = (const float*)d_in[0];
    const int* Lraw = (const int*)d_in[1];
    float* out = (float*)d_out;

    const int smem_bytes = SMEM_FLOATS * 4;   // 36KB -> 4 CTAs/SM
    cudaFuncSetAttribute(dist_kernel,
                         cudaFuncAttributeMaxDynamicSharedMemorySize, smem_bytes);

    sort_kernel<<<1, 256>>>(Lraw);
    gatherT_kernel<<<N_SAMPLES / 32, 256>>>(F);
    dist_kernel<<<NPAIRS, 256, smem_bytes>>>();
    score_kernel<<<N_SAMPLES / 16, 256>>>();
    final_kernel<<<1, 32>>>(out);
}